// round 16
// baseline (speedup 1.0000x reference)
#include <cuda_runtime.h>
#include <cuda_bf16.h>
#include <cstdint>

#define NB 8
#define NH 16
#define SEQ 1024
#define DDIM 64
#define BM 64
#define BN 64
#define NTH 256
#define LOG2E 1.4426950408889634f

// SMEM (80KB/CTA -> 2 CTAs/SM):
//  Q hi/lo 16KB; 2 KV buffers of 32KB, each = [half0 16KB][half1 16KB],
//  half block = [KH 4K][KL 4K][VH 4K][VL 4K] (matches g_kv global layout).
#define SQH 0
#define SQL 8192
#define SBUF 16384
#define BUFSTRIDE 32768
#define HALFSTRIDE 16384
#define SMTOT 81920

// g_kv: per (bh, 32-key group): 16KB block [KH|KL|VH|VL], pre-swizzled.
__device__ unsigned char g_kv[(size_t)NB * NH * 32 * 16384];

__device__ __forceinline__ uint32_t smem_u32(const void* p) {
    uint32_t a;
    asm("{ .reg .u64 t; cvta.to.shared.u64 t, %1; cvt.u32.u64 %0, t; }" : "=r"(a) : "l"(p));
    return a;
}
__device__ __forceinline__ uint32_t sw(uint32_t o) { return o ^ ((o >> 3) & 0x70); }

__device__ __forceinline__ void ldsm4(uint32_t& r0, uint32_t& r1, uint32_t& r2, uint32_t& r3,
                                      uint32_t a) {
    asm volatile("ldmatrix.sync.aligned.m8n8.x4.shared.b16 {%0,%1,%2,%3},[%4];"
                 : "=r"(r0), "=r"(r1), "=r"(r2), "=r"(r3) : "r"(a));
}
__device__ __forceinline__ void ldsm4t(uint32_t& r0, uint32_t& r1, uint32_t& r2, uint32_t& r3,
                                       uint32_t a) {
    asm volatile("ldmatrix.sync.aligned.m8n8.x4.trans.shared.b16 {%0,%1,%2,%3},[%4];"
                 : "=r"(r0), "=r"(r1), "=r"(r2), "=r"(r3) : "r"(a));
}
__device__ __forceinline__ void mma16816(float* c, uint32_t a0, uint32_t a1, uint32_t a2,
                                         uint32_t a3, uint32_t b0, uint32_t b1) {
    asm volatile("mma.sync.aligned.m16n8k16.row.col.f32.bf16.bf16.f32 "
                 "{%0,%1,%2,%3},{%4,%5,%6,%7},{%8,%9},{%0,%1,%2,%3};"
                 : "+f"(c[0]), "+f"(c[1]), "+f"(c[2]), "+f"(c[3])
                 : "r"(a0), "r"(a1), "r"(a2), "r"(a3), "r"(b0), "r"(b1));
}
__device__ __forceinline__ void split2(float x0, float x1, uint32_t& hi, uint32_t& lo) {
    uint32_t hh;
    asm("cvt.rn.bf16x2.f32 %0, %1, %2;" : "=r"(hh) : "f"(x1), "f"(x0));
    float h0 = __uint_as_float(hh << 16);
    float h1 = __uint_as_float(hh & 0xffff0000u);
    float l0 = x0 - h0, l1 = x1 - h1;
    uint32_t ll;
    asm("cvt.rn.bf16x2.f32 %0, %1, %2;" : "=r"(ll) : "f"(l1), "f"(l0));
    hi = hh; lo = ll;
}
__device__ __forceinline__ void mbar_init(uint32_t mb, uint32_t cnt) {
    asm volatile("mbarrier.init.shared.b64 [%0], %1;" :: "r"(mb), "r"(cnt) : "memory");
}
__device__ __forceinline__ void mbar_arrive(uint32_t mb) {
    asm volatile("mbarrier.arrive.shared.b64 _, [%0];" :: "r"(mb) : "memory");
}
__device__ __forceinline__ void mbar_expect_tx(uint32_t mb, uint32_t bytes) {
    asm volatile("mbarrier.arrive.expect_tx.shared.b64 _, [%0], %1;"
                 :: "r"(mb), "r"(bytes) : "memory");
}
__device__ __forceinline__ void bulk_ld(uint32_t dst, const void* src, uint32_t bytes,
                                        uint32_t mb) {
    asm volatile("cp.async.bulk.shared::cta.global.mbarrier::complete_tx::bytes "
                 "[%0], [%1], %2, [%3];"
                 :: "r"(dst), "l"(src), "r"(bytes), "r"(mb) : "memory");
}
__device__ __forceinline__ void mbar_wait(uint32_t mb, uint32_t ph) {
    asm volatile(
        "{\n\t.reg .pred P1;\n\t"
        "W%=:\n\t"
        "mbarrier.try_wait.parity.acquire.cta.shared::cta.b64 P1, [%0], %1, 0x989680;\n\t"
        "@P1 bra.uni D%=;\n\t"
        "bra.uni W%=;\n\t"
        "D%=:\n\t}"
        :: "r"(mb), "r"(ph) : "memory");
}

// ---- prepass: K,V fp32 -> bf16 hi/lo, pre-swizzled blocked layout ----
__global__ __launch_bounds__(256)
void conv_kv(const float4* __restrict__ k4, const float4* __restrict__ v4)
{
    const int i = blockIdx.x * 256 + threadIdx.x;   // one float4 each
    const int e   = i << 2;
    const int bh  = e >> 16;
    const int rem = e & 65535;
    const int n   = rem >> 6;
    const int d   = rem & 63;
    unsigned char* blk = g_kv + ((size_t)(bh * 32 + (n >> 5)) << 14);
    const uint32_t off = sw((uint32_t)(n & 31) * 128 + (uint32_t)d * 2);
    float4 a = k4[i];
    uint2 hi, lo;
    split2(a.x, a.y, hi.x, lo.x);
    split2(a.z, a.w, hi.y, lo.y);
    *(uint2*)(blk + off)         = hi;
    *(uint2*)(blk + 4096 + off)  = lo;
    float4 b = v4[i];
    split2(b.x, b.y, hi.x, lo.x);
    split2(b.z, b.w, hi.y, lo.y);
    *(uint2*)(blk + 8192 + off)  = hi;
    *(uint2*)(blk + 12288 + off) = lo;
}

__global__ __launch_bounds__(NTH, 2)
void attn_mma(const float* __restrict__ q, const int* __restrict__ mask,
              const float* __restrict__ bias, float* __restrict__ out)
{
    extern __shared__ char smem[];
    __shared__ int s_len;
    __shared__ float s_li[64];
    __shared__ __align__(8) unsigned long long mbf[2][2];  // full  [half][buf], cnt 1
    __shared__ __align__(8) unsigned long long mbe[2][2];  // empty [half][buf], cnt 128
    const int tid  = threadIdx.x;
    const int lane = tid & 31;
    const int w    = tid >> 5;
    const int w_m  = w & 3;
    const int w_n  = w >> 2;        // key half: keys 32*w_n..+31 of each tile
    const int nh   = 32 * w_n;
    const int rowg = 16 * w_m;
    const int m0   = blockIdx.x * BM;
    const int h    = blockIdx.y;
    const int b    = blockIdx.z;
    const int bh   = b * NH + h;
    const uint32_t sb = smem_u32(smem);

    const uint32_t mbf_a[2] = { smem_u32(&mbf[w_n][0]), smem_u32(&mbf[w_n][1]) };
    const uint32_t mbe_a[2] = { smem_u32(&mbe[w_n][0]), smem_u32(&mbe[w_n][1]) };
    const unsigned char* gsrc = g_kv + ((size_t)(bh * 32 + w_n) << 14);  // +32KB per tile

    if (tid == 0) {
        s_len = 0;
        #pragma unroll
        for (int hh = 0; hh < 2; hh++)
            #pragma unroll
            for (int bb = 0; bb < 2; bb++) {
                mbar_init(smem_u32(&mbf[hh][bb]), 1);
                mbar_init(smem_u32(&mbe[hh][bb]), 128);
            }
    }
    __syncthreads();

    // ---- prologue: elected thread per half bulk-loads tiles 0 and 1 ----
    if ((tid & 127) == 0) {
        #pragma unroll
        for (int tt = 0; tt < 2; tt++) {
            uint32_t dst = sb + SBUF + (uint32_t)tt * BUFSTRIDE + (uint32_t)w_n * HALFSTRIDE;
            mbar_expect_tx(mbf_a[tt], 16384);
            bulk_ld(dst, gsrc + (size_t)tt * 32768, 16384, mbf_a[tt]);
        }
    }

    {   // valid length (mask int32 0/1, monotone prefix)
        const int* mb = mask + (size_t)b * SEQ;
        int part = 0;
        for (int i = tid; i < SEQ; i += NTH) part += (mb[i] != 0);
        #pragma unroll
        for (int o = 16; o > 0; o >>= 1) part += __shfl_xor_sync(0xffffffffu, part, o);
        if (lane == 0) atomicAdd(&s_len, part);
    }

    // ---- Q tile fp32 -> bf16 hi/lo, swizzled [row][d] 128B rows ----
    {
        const int row  = tid >> 2;                 // 0..63
        const int colf = (tid & 3) * 16;
        const float* qrow = q + (((size_t)bh) * SEQ + m0 + row) * DDIM + colf;
        #pragma unroll
        for (int c = 0; c < 2; c++) {
            float4 t0 = *(const float4*)(qrow + 8 * c);
            float4 t1 = *(const float4*)(qrow + 8 * c + 4);
            uint4 hv, lv;
            split2(t0.x, t0.y, hv.x, lv.x);
            split2(t0.z, t0.w, hv.y, lv.y);
            split2(t1.x, t1.y, hv.z, lv.z);
            split2(t1.z, t1.w, hv.w, lv.w);
            uint32_t off = sw(row * 128 + colf * 2 + 16 * c);
            *(uint4*)(smem + SQH + off) = hv;
            *(uint4*)(smem + SQL + off) = lv;
        }
    }
    __syncthreads();
    const int len = s_len;
    const int n_tiles = (len + BN - 1) / BN;

    const int r8  = (lane & 7) + ((lane >> 3) & 1) * 8;
    const int c16 = ((lane >> 4) & 1) * 16;

    float o[8][4];
    #pragma unroll
    for (int i = 0; i < 8; i++)
        #pragma unroll
        for (int j = 0; j < 4; j++) o[i][j] = 0.0f;
    float li1 = 0.0f, li2 = 0.0f;

    const float* bp1 = bias + ((size_t)h * SEQ + (m0 + rowg + (lane >> 2))) * SEQ;
    const float* bp2 = bp1 + 8 * SEQ;

    for (int t = 0; t < n_tiles; t++) {
        const int n0 = t * BN;
        const int buf = t & 1;
        const uint32_t ph = (uint32_t)((t >> 1) & 1);
        const uint32_t khalf = sb + SBUF + (uint32_t)buf * BUFSTRIDE + (uint32_t)w_n * HALFSTRIDE;

        // ---- bias prefetch (pre-scaled by log2(e)) ----
        float2 bb1[4], bb2[4];
        #pragma unroll
        for (int nb = 0; nb < 4; nb++) {
            int c = n0 + nh + 8 * nb + (lane & 3) * 2;
            bb1[nb] = *(const float2*)(bp1 + c);
            bb2[nb] = *(const float2*)(bp2 + c);
            bb1[nb].x *= LOG2E; bb1[nb].y *= LOG2E;
            bb2[nb].x *= LOG2E; bb2[nb].y *= LOG2E;
        }

        // ---- data(t) ready? (acquire: TMA writes visible to this thread) ----
        mbar_wait(mbf_a[buf], ph);

        // ---- GEMM1: S = QK^T, 3-way split; 4 independent accumulator chains,
        //      dependent MMAs 3 issues apart (asm order = issue order) ----
        float s[4][4];
        #pragma unroll
        for (int i = 0; i < 4; i++)
            #pragma unroll
            for (int j = 0; j < 4; j++) s[i][j] = 0.0f;
        #pragma unroll
        for (int kbk = 0; kbk < 4; kbk++) {
            uint32_t qoff = sw((rowg + r8) * 128 + 32 * kbk + c16);
            uint32_t a0, a1, a2, a3, e0, e1, e2, e3;
            ldsm4(a0, a1, a2, a3, sb + SQH + qoff);
            ldsm4(e0, e1, e2, e3, sb + SQL + qoff);
            uint32_t boff0 = sw((r8) * 128 + 32 * kbk + c16);
            uint32_t boff1 = sw((16 + r8) * 128 + 32 * kbk + c16);
            uint32_t h00, h01, h02, h03, h10, h11, h12, h13;
            uint32_t l00, l01, l02, l03, l10, l11, l12, l13;
            ldsm4(h00, h01, h02, h03, khalf + boff0);
            ldsm4(h10, h11, h12, h13, khalf + boff1);
            ldsm4(l00, l01, l02, l03, khalf + 4096 + boff0);
            ldsm4(l10, l11, l12, l13, khalf + 4096 + boff1);
            // hi*hi across all 4 accumulators
            mma16816(s[0], a0, a1, a2, a3, h00, h02);
            mma16816(s[1], a0, a1, a2, a3, h01, h03);
            mma16816(s[2], a0, a1, a2, a3, h10, h12);
            mma16816(s[3], a0, a1, a2, a3, h11, h13);
            // lo*hi
            mma16816(s[0], e0, e1, e2, e3, h00, h02);
            mma16816(s[1], e0, e1, e2, e3, h01, h03);
            mma16816(s[2], e0, e1, e2, e3, h10, h12);
            mma16816(s[3], e0, e1, e2, e3, h11, h13);
            // hi*lo
            mma16816(s[0], a0, a1, a2, a3, l00, l02);
            mma16816(s[1], a0, a1, a2, a3, l01, l03);
            mma16816(s[2], a0, a1, a2, a3, l10, l12);
            mma16816(s[3], a0, a1, a2, a3, l11, l13);
        }

        // ---- softmax: p = exp2(s*log2e + bias*log2e), no max-sub ----
        uint32_t pah[2][4], pal[2][4];
        #pragma unroll
        for (int nb = 0; nb < 4; nb++) {
            int n = n0 + nh + 8 * nb + (lane & 3) * 2;
            float p0 = (n     < len) ? exp2f(fmaf(s[nb][0], LOG2E, bb1[nb].x)) : 0.0f;
            float p1 = (n + 1 < len) ? exp2f(fmaf(s[nb][1], LOG2E, bb1[nb].y)) : 0.0f;
            float p2 = (n     < len) ? exp2f(fmaf(s[nb][2], LOG2E, bb2[nb].x)) : 0.0f;
            float p3 = (n + 1 < len) ? exp2f(fmaf(s[nb][3], LOG2E, bb2[nb].y)) : 0.0f;
            li1 += p0 + p1;
            li2 += p2 + p3;
            split2(p0, p1, pah[nb >> 1][(nb & 1) * 2],     pal[nb >> 1][(nb & 1) * 2]);
            split2(p2, p3, pah[nb >> 1][(nb & 1) * 2 + 1], pal[nb >> 1][(nb & 1) * 2 + 1]);
        }

        // ---- GEMM2: O(partial) += P V; nbp pairs, 4-chain rotation ----
        const uint32_t vh_ = khalf + 8192;
        const uint32_t vl_ = khalf + 12288;
        #pragma unroll
        for (int kk = 0; kk < 2; kk++) {
            #pragma unroll
            for (int np = 0; np < 2; np++) {   // nbp pair: {2np, 2np+1}
                uint32_t voff0 = sw((16 * kk + r8) * 128 + 32 * (2 * np)     + c16);
                uint32_t voff1 = sw((16 * kk + r8) * 128 + 32 * (2 * np + 1) + c16);
                uint32_t x0, x1, x2, x3, y0, y1, y2, y3;
                uint32_t u0, u1, u2, u3, v0, v1, v2, v3;
                ldsm4t(x0, x1, x2, x3, vh_ + voff0);
                ldsm4t(y0, y1, y2, y3, vh_ + voff1);
                ldsm4t(u0, u1, u2, u3, vl_ + voff0);
                ldsm4t(v0, v1, v2, v3, vl_ + voff1);
                float* oa = o[4 * np];
                float* ob = o[4 * np + 1];
                float* oc = o[4 * np + 2];
                float* od = o[4 * np + 3];
                // pah * vh
                mma16816(oa, pah[kk][0], pah[kk][1], pah[kk][2], pah[kk][3], x0, x1);
                mma16816(ob, pah[kk][0], pah[kk][1], pah[kk][2], pah[kk][3], x2, x3);
                mma16816(oc, pah[kk][0], pah[kk][1], pah[kk][2], pah[kk][3], y0, y1);
                mma16816(od, pah[kk][0], pah[kk][1], pah[kk][2], pah[kk][3], y2, y3);
                // pal * vh
                mma16816(oa, pal[kk][0], pal[kk][1], pal[kk][2], pal[kk][3], x0, x1);
                mma16816(ob, pal[kk][0], pal[kk][1], pal[kk][2], pal[kk][3], x2, x3);
                mma16816(oc, pal[kk][0], pal[kk][1], pal[kk][2], pal[kk][3], y0, y1);
                mma16816(od, pal[kk][0], pal[kk][1], pal[kk][2], pal[kk][3], y2, y3);
                // pah * vl
                mma16816(oa, pah[kk][0], pah[kk][1], pah[kk][2], pah[kk][3], u0, u1);
                mma16816(ob, pah[kk][0], pah[kk][1], pah[kk][2], pah[kk][3], u2, u3);
                mma16816(oc, pah[kk][0], pah[kk][1], pah[kk][2], pah[kk][3], v0, v1);
                mma16816(od, pah[kk][0], pah[kk][1], pah[kk][2], pah[kk][3], v2, v3);
            }
        }

        // ---- signal buffer free; elected refills it with tile t+2 ----
        mbar_arrive(mbe_a[buf]);
        if ((tid & 127) == 0 && t + 2 < n_tiles) {
            mbar_wait(mbe_a[buf], ph);   // all 128 of this half done reading
            uint32_t dst = sb + SBUF + (uint32_t)buf * BUFSTRIDE + (uint32_t)w_n * HALFSTRIDE;
            mbar_expect_tx(mbf_a[buf], 16384);
            bulk_ld(dst, gsrc + (size_t)(t + 2) * 32768, 16384, mbf_a[buf]);
        }
    }

    // ---- reduce li across the quad (lanes l^1, l^2 hold the same rows) ----
    li1 += __shfl_xor_sync(0xffffffffu, li1, 1);
    li1 += __shfl_xor_sync(0xffffffffu, li1, 2);
    li2 += __shfl_xor_sync(0xffffffffu, li2, 1);
    li2 += __shfl_xor_sync(0xffffffffu, li2, 2);

    // ---- combine the two key-halves through smem ----
    __syncthreads();   // all warps past their loop; safe to alias buffer space
    float* oshare = (float*)(smem + SBUF);   // [64][64] fp32 = 16KB
    const int r1 = rowg + (lane >> 2);
    if (w_n == 1) {
        #pragma unroll
        for (int nb = 0; nb < 8; nb++) {
            int c = 8 * nb + (lane & 3) * 2;
            *(float2*)(oshare + r1 * 64 + c)       = make_float2(o[nb][0], o[nb][1]);
            *(float2*)(oshare + (r1 + 8) * 64 + c) = make_float2(o[nb][2], o[nb][3]);
        }
        if ((lane & 3) == 0) {
            s_li[r1]     = li1;
            s_li[r1 + 8] = li2;
        }
    }
    __syncthreads();

    if (w_n == 0) {
        const float lt1 = li1 + s_li[r1];
        const float lt2 = li2 + s_li[r1 + 8];
        const float inv1 = ((m0 + r1)     < len) ? (1.0f / lt1) : 0.0f;
        const float inv2 = ((m0 + r1 + 8) < len) ? (1.0f / lt2) : 0.0f;
        float* o1 = out + ((size_t)b * SEQ + m0 + r1) * (NH * DDIM) + (size_t)h * DDIM;
        float* o2 = o1 + 8 * (NH * DDIM);
        #pragma unroll
        for (int nb = 0; nb < 8; nb++) {
            int c = 8 * nb + (lane & 3) * 2;
            float2 q1 = *(const float2*)(oshare + r1 * 64 + c);
            float2 q2 = *(const float2*)(oshare + (r1 + 8) * 64 + c);
            float2 w1 = {(o[nb][0] + q1.x) * inv1, (o[nb][1] + q1.y) * inv1};
            float2 w2 = {(o[nb][2] + q2.x) * inv2, (o[nb][3] + q2.y) * inv2};
            *(float2*)(o1 + c) = w1;
            *(float2*)(o2 + c) = w2;
        }
    }
}

extern "C" void kernel_launch(void* const* d_in, const int* in_sizes, int n_in,
                              void* d_out, int out_size)
{
    const float* q    = (const float*)d_in[0];
    const float* k    = (const float*)d_in[1];
    const float* v    = (const float*)d_in[2];
    const int*   mask = (const int*)d_in[3];
    const float* bias = (const float*)d_in[4];
    float* out = (float*)d_out;

    conv_kv<<<(NB * NH * SEQ * DDIM) / 4 / 256, 256>>>((const float4*)k, (const float4*)v);

    cudaFuncSetAttribute(attn_mma, cudaFuncAttributeMaxDynamicSharedMemorySize, SMTOT);
    dim3 grid(SEQ / BM, NH, NB);
    attn_mma<<<grid, NTH, SMTOT>>>(q, mask, bias, out);
}

// round 17
// speedup vs baseline: 1.0749x; 1.0749x over previous
#include <cuda_runtime.h>
#include <cuda_bf16.h>
#include <cstdint>

#define NB 8
#define NH 16
#define SEQ 1024
#define DDIM 64
#define BM 64
#define BN 64
#define NTH 256
#define LOG2E 1.4426950408889634f

// SMEM (112KB/CTA -> 2 CTAs/SM):
//  Q hi/lo 16KB; 3-deep KV ring of 32KB buffers, each = [half0 16KB][half1 16KB],
//  half block = [KH 4K][KL 4K][VH 4K][VL 4K] (matches g_kv global layout).
#define SQH 0
#define SQL 8192
#define SBUF 16384
#define BUFSTRIDE 32768
#define HALFSTRIDE 16384
#define NBUF 3
#define SMTOT (SBUF + NBUF * BUFSTRIDE)   // 114688

// g_kv: per (bh, 32-key group): 16KB block [KH|KL|VH|VL], pre-swizzled.
__device__ unsigned char g_kv[(size_t)NB * NH * 32 * 16384];

__device__ __forceinline__ uint32_t smem_u32(const void* p) {
    uint32_t a;
    asm("{ .reg .u64 t; cvta.to.shared.u64 t, %1; cvt.u32.u64 %0, t; }" : "=r"(a) : "l"(p));
    return a;
}
__device__ __forceinline__ uint32_t sw(uint32_t o) { return o ^ ((o >> 3) & 0x70); }

__device__ __forceinline__ void ldsm4(uint32_t& r0, uint32_t& r1, uint32_t& r2, uint32_t& r3,
                                      uint32_t a) {
    asm volatile("ldmatrix.sync.aligned.m8n8.x4.shared.b16 {%0,%1,%2,%3},[%4];"
                 : "=r"(r0), "=r"(r1), "=r"(r2), "=r"(r3) : "r"(a));
}
__device__ __forceinline__ void ldsm4t(uint32_t& r0, uint32_t& r1, uint32_t& r2, uint32_t& r3,
                                       uint32_t a) {
    asm volatile("ldmatrix.sync.aligned.m8n8.x4.trans.shared.b16 {%0,%1,%2,%3},[%4];"
                 : "=r"(r0), "=r"(r1), "=r"(r2), "=r"(r3) : "r"(a));
}
__device__ __forceinline__ void mma16816(float* c, uint32_t a0, uint32_t a1, uint32_t a2,
                                         uint32_t a3, uint32_t b0, uint32_t b1) {
    asm volatile("mma.sync.aligned.m16n8k16.row.col.f32.bf16.bf16.f32 "
                 "{%0,%1,%2,%3},{%4,%5,%6,%7},{%8,%9},{%0,%1,%2,%3};"
                 : "+f"(c[0]), "+f"(c[1]), "+f"(c[2]), "+f"(c[3])
                 : "r"(a0), "r"(a1), "r"(a2), "r"(a3), "r"(b0), "r"(b1));
}
__device__ __forceinline__ void split2(float x0, float x1, uint32_t& hi, uint32_t& lo) {
    uint32_t hh;
    asm("cvt.rn.bf16x2.f32 %0, %1, %2;" : "=r"(hh) : "f"(x1), "f"(x0));
    float h0 = __uint_as_float(hh << 16);
    float h1 = __uint_as_float(hh & 0xffff0000u);
    float l0 = x0 - h0, l1 = x1 - h1;
    uint32_t ll;
    asm("cvt.rn.bf16x2.f32 %0, %1, %2;" : "=r"(ll) : "f"(l1), "f"(l0));
    hi = hh; lo = ll;
}
__device__ __forceinline__ void mbar_init(uint32_t mb, uint32_t cnt) {
    asm volatile("mbarrier.init.shared.b64 [%0], %1;" :: "r"(mb), "r"(cnt) : "memory");
}
__device__ __forceinline__ void mbar_arrive(uint32_t mb) {
    asm volatile("mbarrier.arrive.shared.b64 _, [%0];" :: "r"(mb) : "memory");
}
__device__ __forceinline__ void mbar_expect_tx(uint32_t mb, uint32_t bytes) {
    asm volatile("mbarrier.arrive.expect_tx.shared.b64 _, [%0], %1;"
                 :: "r"(mb), "r"(bytes) : "memory");
}
__device__ __forceinline__ void bulk_ld(uint32_t dst, const void* src, uint32_t bytes,
                                        uint32_t mb) {
    asm volatile("cp.async.bulk.shared::cta.global.mbarrier::complete_tx::bytes "
                 "[%0], [%1], %2, [%3];"
                 :: "r"(dst), "l"(src), "r"(bytes), "r"(mb) : "memory");
}
__device__ __forceinline__ void mbar_wait(uint32_t mb, uint32_t ph) {
    asm volatile(
        "{\n\t.reg .pred P1;\n\t"
        "W%=:\n\t"
        "mbarrier.try_wait.parity.acquire.cta.shared::cta.b64 P1, [%0], %1, 0x989680;\n\t"
        "@P1 bra.uni D%=;\n\t"
        "bra.uni W%=;\n\t"
        "D%=:\n\t}"
        :: "r"(mb), "r"(ph) : "memory");
}

// ---- prepass: K,V fp32 -> bf16 hi/lo, pre-swizzled blocked layout ----
__global__ __launch_bounds__(256)
void conv_kv(const float4* __restrict__ k4, const float4* __restrict__ v4)
{
    const int i = blockIdx.x * 256 + threadIdx.x;   // one float4 each
    const int e   = i << 2;
    const int bh  = e >> 16;
    const int rem = e & 65535;
    const int n   = rem >> 6;
    const int d   = rem & 63;
    unsigned char* blk = g_kv + ((size_t)(bh * 32 + (n >> 5)) << 14);
    const uint32_t off = sw((uint32_t)(n & 31) * 128 + (uint32_t)d * 2);
    float4 a = k4[i];
    uint2 hi, lo;
    split2(a.x, a.y, hi.x, lo.x);
    split2(a.z, a.w, hi.y, lo.y);
    *(uint2*)(blk + off)         = hi;
    *(uint2*)(blk + 4096 + off)  = lo;
    float4 b = v4[i];
    split2(b.x, b.y, hi.x, lo.x);
    split2(b.z, b.w, hi.y, lo.y);
    *(uint2*)(blk + 8192 + off)  = hi;
    *(uint2*)(blk + 12288 + off) = lo;
}

__global__ __launch_bounds__(NTH, 2)
void attn_mma(const float* __restrict__ q, const int* __restrict__ mask,
              const float* __restrict__ bias, float* __restrict__ out)
{
    extern __shared__ char smem[];
    __shared__ int s_len;
    __shared__ float s_li[64];
    __shared__ __align__(8) unsigned long long mbf[2][NBUF];  // full  [half][buf], cnt 1
    __shared__ __align__(8) unsigned long long mbe[2][NBUF];  // empty [half][buf], cnt 128
    const int tid  = threadIdx.x;
    const int lane = tid & 31;
    const int w    = tid >> 5;
    const int w_m  = w & 3;
    const int w_n  = w >> 2;        // key half: keys 32*w_n..+31 of each tile
    const int nh   = 32 * w_n;
    const int rowg = 16 * w_m;
    const int m0   = blockIdx.x * BM;
    const int h    = blockIdx.y;
    const int b    = blockIdx.z;
    const int bh   = b * NH + h;
    const uint32_t sb = smem_u32(smem);

    const uint32_t mbf_a[NBUF] = { smem_u32(&mbf[w_n][0]), smem_u32(&mbf[w_n][1]),
                                   smem_u32(&mbf[w_n][2]) };
    const uint32_t mbe_a[NBUF] = { smem_u32(&mbe[w_n][0]), smem_u32(&mbe[w_n][1]),
                                   smem_u32(&mbe[w_n][2]) };
    const unsigned char* gsrc = g_kv + ((size_t)(bh * 32 + w_n) << 14);  // +32KB per tile

    if (tid == 0) {
        s_len = 0;
        #pragma unroll
        for (int hh = 0; hh < 2; hh++)
            #pragma unroll
            for (int bb = 0; bb < NBUF; bb++) {
                mbar_init(smem_u32(&mbf[hh][bb]), 1);
                mbar_init(smem_u32(&mbe[hh][bb]), 128);
            }
    }
    __syncthreads();

    // ---- prologue: elected thread per half bulk-loads tiles 0..2 ----
    if ((tid & 127) == 0) {
        #pragma unroll
        for (int tt = 0; tt < NBUF; tt++) {
            uint32_t dst = sb + SBUF + (uint32_t)tt * BUFSTRIDE + (uint32_t)w_n * HALFSTRIDE;
            mbar_expect_tx(mbf_a[tt], 16384);
            bulk_ld(dst, gsrc + (size_t)tt * 32768, 16384, mbf_a[tt]);
        }
    }

    {   // valid length (mask int32 0/1, monotone prefix)
        const int* mb = mask + (size_t)b * SEQ;
        int part = 0;
        for (int i = tid; i < SEQ; i += NTH) part += (mb[i] != 0);
        #pragma unroll
        for (int o = 16; o > 0; o >>= 1) part += __shfl_xor_sync(0xffffffffu, part, o);
        if (lane == 0) atomicAdd(&s_len, part);
    }

    // ---- Q tile fp32 -> bf16 hi/lo, swizzled [row][d] 128B rows ----
    {
        const int row  = tid >> 2;                 // 0..63
        const int colf = (tid & 3) * 16;
        const float* qrow = q + (((size_t)bh) * SEQ + m0 + row) * DDIM + colf;
        #pragma unroll
        for (int c = 0; c < 2; c++) {
            float4 t0 = *(const float4*)(qrow + 8 * c);
            float4 t1 = *(const float4*)(qrow + 8 * c + 4);
            uint4 hv, lv;
            split2(t0.x, t0.y, hv.x, lv.x);
            split2(t0.z, t0.w, hv.y, lv.y);
            split2(t1.x, t1.y, hv.z, lv.z);
            split2(t1.z, t1.w, hv.w, lv.w);
            uint32_t off = sw(row * 128 + colf * 2 + 16 * c);
            *(uint4*)(smem + SQH + off) = hv;
            *(uint4*)(smem + SQL + off) = lv;
        }
    }
    __syncthreads();
    const int len = s_len;
    const int n_tiles = (len + BN - 1) / BN;

    const int r8  = (lane & 7) + ((lane >> 3) & 1) * 8;
    const int c16 = ((lane >> 4) & 1) * 16;

    float o[8][4];
    #pragma unroll
    for (int i = 0; i < 8; i++)
        #pragma unroll
        for (int j = 0; j < 4; j++) o[i][j] = 0.0f;
    float li1 = 0.0f, li2 = 0.0f;

    const float* bp1 = bias + ((size_t)h * SEQ + (m0 + rowg + (lane >> 2))) * SEQ;
    const float* bp2 = bp1 + 8 * SEQ;

    int buf = 0;            // ring position, t mod 3
    uint32_t ph = 0;        // use-count parity for this buffer

    for (int t = 0; t < n_tiles; t++) {
        const int n0 = t * BN;
        const uint32_t khalf = sb + SBUF + (uint32_t)buf * BUFSTRIDE + (uint32_t)w_n * HALFSTRIDE;

        // ---- bias prefetch (pre-scaled by log2(e)) ----
        float2 bb1[4], bb2[4];
        #pragma unroll
        for (int nb = 0; nb < 4; nb++) {
            int c = n0 + nh + 8 * nb + (lane & 3) * 2;
            bb1[nb] = *(const float2*)(bp1 + c);
            bb2[nb] = *(const float2*)(bp2 + c);
            bb1[nb].x *= LOG2E; bb1[nb].y *= LOG2E;
            bb2[nb].x *= LOG2E; bb2[nb].y *= LOG2E;
        }

        // ---- data(t) ready? (acquire: TMA writes visible to this thread) ----
        mbar_wait(mbf_a[buf], ph);

        // ---- GEMM1: S = QK^T over this warp's 32-key half, 3-way split ----
        float s[4][4];
        #pragma unroll
        for (int i = 0; i < 4; i++)
            #pragma unroll
            for (int j = 0; j < 4; j++) s[i][j] = 0.0f;
        #pragma unroll
        for (int kbk = 0; kbk < 4; kbk++) {
            uint32_t qoff = sw((rowg + r8) * 128 + 32 * kbk + c16);
            uint32_t a0, a1, a2, a3, e0, e1, e2, e3;
            ldsm4(a0, a1, a2, a3, sb + SQH + qoff);
            ldsm4(e0, e1, e2, e3, sb + SQL + qoff);
            #pragma unroll
            for (int nbp = 0; nbp < 2; nbp++) {
                uint32_t boff = sw((16 * nbp + r8) * 128 + 32 * kbk + c16);
                uint32_t bh0, bh1, bh2, bh3, bl0, bl1, bl2, bl3;
                ldsm4(bh0, bh1, bh2, bh3, khalf + boff);
                ldsm4(bl0, bl1, bl2, bl3, khalf + 4096 + boff);
                mma16816(s[2 * nbp],     a0, a1, a2, a3, bh0, bh2);
                mma16816(s[2 * nbp + 1], a0, a1, a2, a3, bh1, bh3);
                mma16816(s[2 * nbp],     e0, e1, e2, e3, bh0, bh2);
                mma16816(s[2 * nbp + 1], e0, e1, e2, e3, bh1, bh3);
                mma16816(s[2 * nbp],     a0, a1, a2, a3, bl0, bl2);
                mma16816(s[2 * nbp + 1], a0, a1, a2, a3, bl1, bl3);
            }
        }

        // ---- softmax: p = exp2(s*log2e + bias*log2e), no max-sub ----
        uint32_t pah[2][4], pal[2][4];
        #pragma unroll
        for (int nb = 0; nb < 4; nb++) {
            int n = n0 + nh + 8 * nb + (lane & 3) * 2;
            float p0 = (n     < len) ? exp2f(fmaf(s[nb][0], LOG2E, bb1[nb].x)) : 0.0f;
            float p1 = (n + 1 < len) ? exp2f(fmaf(s[nb][1], LOG2E, bb1[nb].y)) : 0.0f;
            float p2 = (n     < len) ? exp2f(fmaf(s[nb][2], LOG2E, bb2[nb].x)) : 0.0f;
            float p3 = (n + 1 < len) ? exp2f(fmaf(s[nb][3], LOG2E, bb2[nb].y)) : 0.0f;
            li1 += p0 + p1;
            li2 += p2 + p3;
            split2(p0, p1, pah[nb >> 1][(nb & 1) * 2],     pal[nb >> 1][(nb & 1) * 2]);
            split2(p2, p3, pah[nb >> 1][(nb & 1) * 2 + 1], pal[nb >> 1][(nb & 1) * 2 + 1]);
        }

        // ---- GEMM2: O(partial) += P V over this warp's 32 keys ----
        const uint32_t vh_ = khalf + 8192;
        const uint32_t vl_ = khalf + 12288;
        #pragma unroll
        for (int kk = 0; kk < 2; kk++) {
            #pragma unroll
            for (int nbp = 0; nbp < 4; nbp++) {
                uint32_t voff = sw((16 * kk + r8) * 128 + 32 * nbp + c16);
                uint32_t vh0, vh1, vh2, vh3, vl0, vl1, vl2, vl3;
                ldsm4t(vh0, vh1, vh2, vh3, vh_ + voff);
                ldsm4t(vl0, vl1, vl2, vl3, vl_ + voff);
                mma16816(o[2 * nbp],     pah[kk][0], pah[kk][1], pah[kk][2], pah[kk][3], vh0, vh1);
                mma16816(o[2 * nbp + 1], pah[kk][0], pah[kk][1], pah[kk][2], pah[kk][3], vh2, vh3);
                mma16816(o[2 * nbp],     pal[kk][0], pal[kk][1], pal[kk][2], pal[kk][3], vh0, vh1);
                mma16816(o[2 * nbp + 1], pal[kk][0], pal[kk][1], pal[kk][2], pal[kk][3], vh2, vh3);
                mma16816(o[2 * nbp],     pah[kk][0], pah[kk][1], pah[kk][2], pah[kk][3], vl0, vl1);
                mma16816(o[2 * nbp + 1], pah[kk][0], pah[kk][1], pah[kk][2], pah[kk][3], vl2, vl3);
            }
        }

        // ---- signal buffer free; elected refills it with tile t+3 ----
        mbar_arrive(mbe_a[buf]);
        if ((tid & 127) == 0 && t + NBUF < n_tiles) {
            mbar_wait(mbe_a[buf], ph);   // 2 tiles of slack; rarely blocks
            uint32_t dst = sb + SBUF + (uint32_t)buf * BUFSTRIDE + (uint32_t)w_n * HALFSTRIDE;
            mbar_expect_tx(mbf_a[buf], 16384);
            bulk_ld(dst, gsrc + (size_t)(t + NBUF) * 32768, 16384, mbf_a[buf]);
        }
        if (++buf == NBUF) { buf = 0; ph ^= 1; }
    }

    // ---- reduce li across the quad (lanes l^1, l^2 hold the same rows) ----
    li1 += __shfl_xor_sync(0xffffffffu, li1, 1);
    li1 += __shfl_xor_sync(0xffffffffu, li1, 2);
    li2 += __shfl_xor_sync(0xffffffffu, li2, 1);
    li2 += __shfl_xor_sync(0xffffffffu, li2, 2);

    // ---- combine the two key-halves through smem ----
    __syncthreads();   // all warps past their loop; safe to alias buffer space
    float* oshare = (float*)(smem + SBUF);   // [64][64] fp32 = 16KB
    const int r1 = rowg + (lane >> 2);
    if (w_n == 1) {
        #pragma unroll
        for (int nb = 0; nb < 8; nb++) {
            int c = 8 * nb + (lane & 3) * 2;
            *(float2*)(oshare + r1 * 64 + c)       = make_float2(o[nb][0], o[nb][1]);
            *(float2*)(oshare + (r1 + 8) * 64 + c) = make_float2(o[nb][2], o[nb][3]);
        }
        if ((lane & 3) == 0) {
            s_li[r1]     = li1;
            s_li[r1 + 8] = li2;
        }
    }
    __syncthreads();

    if (w_n == 0) {
        const float lt1 = li1 + s_li[r1];
        const float lt2 = li2 + s_li[r1 + 8];
        const float inv1 = ((m0 + r1)     < len) ? (1.0f / lt1) : 0.0f;
        const float inv2 = ((m0 + r1 + 8) < len) ? (1.0f / lt2) : 0.0f;
        float* o1 = out + ((size_t)b * SEQ + m0 + r1) * (NH * DDIM) + (size_t)h * DDIM;
        float* o2 = o1 + 8 * (NH * DDIM);
        #pragma unroll
        for (int nb = 0; nb < 8; nb++) {
            int c = 8 * nb + (lane & 3) * 2;
            float2 q1 = *(const float2*)(oshare + r1 * 64 + c);
            float2 q2 = *(const float2*)(oshare + (r1 + 8) * 64 + c);
            float2 w1 = {(o[nb][0] + q1.x) * inv1, (o[nb][1] + q1.y) * inv1};
            float2 w2 = {(o[nb][2] + q2.x) * inv2, (o[nb][3] + q2.y) * inv2};
            *(float2*)(o1 + c) = w1;
            *(float2*)(o2 + c) = w2;
        }
    }
}

extern "C" void kernel_launch(void* const* d_in, const int* in_sizes, int n_in,
                              void* d_out, int out_size)
{
    const float* q    = (const float*)d_in[0];
    const float* k    = (const float*)d_in[1];
    const float* v    = (const float*)d_in[2];
    const int*   mask = (const int*)d_in[3];
    const float* bias = (const float*)d_in[4];
    float* out = (float*)d_out;

    conv_kv<<<(NB * NH * SEQ * DDIM) / 4 / 256, 256>>>((const float4*)k, (const float4*)v);

    cudaFuncSetAttribute(attn_mma, cudaFuncAttributeMaxDynamicSharedMemorySize, SMTOT);
    dim3 grid(SEQ / BM, NH, NB);
    attn_mma<<<grid, NTH, SMTOT>>>(q, mask, bias, out);
}